// round 1
// baseline (speedup 1.0000x reference)
#include <cuda_runtime.h>
#include <math.h>

// ---------------------------------------------------------------------------
// OneDimEquivalent: z_hist[b, t+1] from recurrence
//   delta^2 = k^2 + u^2 ; g = (1/sqrt(2pi)) * GL128 quad of (1 - tanh(delta z)^2) e^{-z^2/2}
//   v' = 0.8 v + 0.2 u ; k' = k(0.8 + 0.28 g) + 0.52 g v' ; z = 2.1 k'
// Strategy: g is a smooth univariate function of s = delta^2. Build a LUT
// g(s) on device (GL nodes via Newton in double, table via fp32 tanhf), then
// run the scan with a shared-memory LUT + centered linear interpolation.
// One thread per row, state pre-scaled so the critical chain is
// fma -> round -> addr -> LDS.64 -> fma -> fma -> fma  (~61 cyc/step).
// ---------------------------------------------------------------------------

#define B_DIM 4096
#define T_DIM 4096
#define TBL_N 16384          // table entries
#define S_MAX 64.0f          // table covers s = delta^2 in [0, 64]  (delta <= 8)
#define SCALE_S 256.0f       // TBL_N / S_MAX
#define SQRT_SCALE 16.0f     // sqrt(SCALE_S)
#define MAGIC 12582912.0f    // 1.5 * 2^23 : round-to-nearest integer trick
#define TMAX_F 16383.0f
#define INV_SQRT_2PI 0.3989422804014327f

// Quadrature nodes/weights (positive half, symmetric pairs) + LUT
__device__ double g_zn_d[64];     // z_j = 5 * x_j  (positive nodes)
__device__ float  g_zn[64];
__device__ float  g_qw[64];       // 5 * w_j * exp(-z_j^2/2)
__device__ float2 g_table[TBL_N]; // (value, slope-per-index)

// ---------------------------------------------------------------------------
// Kernel 1: Gauss-Legendre nodes/weights for n=128 (positive half).
// Newton from cos guess; 4 double iterations (guess ~1e-4 -> ~1e-15).
// ---------------------------------------------------------------------------
__global__ void gl_nodes_kernel() {
    int i = threadIdx.x;            // 0..63 -> 64 positive roots (n even)
    if (i >= 64) return;
    const int n = 128;
    double x = cos(3.14159265358979323846 * (i + 0.75) / (n + 0.5));

    double pn = 0.0, pnm1 = 0.0;
    #pragma unroll 1
    for (int it = 0; it < 5; ++it) {
        double p0 = 1.0, p1 = x;
        #pragma unroll 1
        for (int j = 2; j <= n; ++j) {
            double p2 = ((2.0 * j - 1.0) * x * p1 - (j - 1.0) * p0) / (double)j;
            p0 = p1; p1 = p2;
        }
        pn = p1; pnm1 = p0;
        double dp = n * (x * pn - pnm1) / (x * x - 1.0);
        x -= pn / dp;
    }
    // final derivative at converged x
    {
        double p0 = 1.0, p1 = x;
        #pragma unroll 1
        for (int j = 2; j <= n; ++j) {
            double p2 = ((2.0 * j - 1.0) * x * p1 - (j - 1.0) * p0) / (double)j;
            p0 = p1; p1 = p2;
        }
        pn = p1; pnm1 = p0;
    }
    double dp = n * (x * pn - pnm1) / (x * x - 1.0);
    double w  = 2.0 / ((1.0 - x * x) * dp * dp);
    double z  = 5.0 * x;                 // node scaled to [-5, 5]
    double q  = 5.0 * w * exp(-0.5 * z * z);
    g_zn_d[i] = z;
    g_zn[i]   = (float)z;
    g_qw[i]   = (float)q;
}

// ---------------------------------------------------------------------------
// Kernel 2: table values  g(s_i),  s_i = i / 256
// ---------------------------------------------------------------------------
__global__ void table_val_kernel() {
    int i = blockIdx.x * blockDim.x + threadIdx.x;
    if (i >= TBL_N) return;
    float s = (float)i * (1.0f / SCALE_S);
    float d = sqrtf(s);
    float acc = 0.0f;
    #pragma unroll 8
    for (int j = 0; j < 64; ++j) {
        float t = tanhf(d * g_zn[j]);
        acc = fmaf(g_qw[j], 1.0f - t * t, acc);
    }
    g_table[i].x = acc * (2.0f * INV_SQRT_2PI);  // x2 for symmetric pairs
}

// ---------------------------------------------------------------------------
// Kernel 3: slopes (centered difference per index step)
// ---------------------------------------------------------------------------
__global__ void table_slope_kernel() {
    int i = blockIdx.x * blockDim.x + threadIdx.x;
    if (i >= TBL_N) return;
    float sl;
    if (i == 0)              sl = g_table[1].x - g_table[0].x;
    else if (i == TBL_N - 1) sl = g_table[TBL_N - 1].x - g_table[TBL_N - 2].x;
    else                     sl = 0.5f * (g_table[i + 1].x - g_table[i - 1].x);
    g_table[i].y = sl;
}

// ---------------------------------------------------------------------------
// Main scan kernel. 32 blocks x 128 threads = 4096 rows (1 thread / row).
// Shared: table (128 KB) + per-warp output staging (stride-33, conflict-free).
// State pre-scaled: K = 16*k so the LUT index is fma(K,K,uus) directly.
// ---------------------------------------------------------------------------
__global__ __launch_bounds__(128, 1)
void scan_kernel(const float* __restrict__ u, float* __restrict__ out) {
    extern __shared__ float smem[];
    float2* s_tbl = (float2*)smem;
    float*  s_out = smem + 2 * TBL_N;        // 128 * 33 floats

    // cooperative table load (float4)
    {
        const float4* gt = (const float4*)g_table;
        float4* st = (float4*)s_tbl;
        #pragma unroll 4
        for (int i = threadIdx.x; i < TBL_N / 2; i += 128) st[i] = gt[i];
    }
    __syncthreads();

    const int tid   = threadIdx.x;
    const int lane  = tid & 31;
    const int wbase = tid & ~31;                  // warp's local row base
    const int row   = blockIdx.x * 128 + tid;

    const float* urow = u + (size_t)row * T_DIM;
    out[(size_t)row * (T_DIM + 1)] = 0.0f;        // z_hist[:,0] = 0

    float* srow = s_out + tid * 33;

    float K = 0.0f, v = 0.0f;
    float ua[32], ub[32];

    auto loadch = [&](float (&b)[32], int c) {
        const float4* p = (const float4*)(urow + c * 32);
        #pragma unroll
        for (int q = 0; q < 8; ++q) {
            float4 t = p[q];
            b[4*q+0] = t.x; b[4*q+1] = t.y; b[4*q+2] = t.z; b[4*q+3] = t.w;
        }
    };

    auto compute = [&](const float (&b)[32], int c) {
        #pragma unroll
        for (int j = 0; j < 32; ++j) {
            float uu  = b[j];
            float us  = uu * SQRT_SCALE;          // off-chain
            float uus = us * us;                  // 256 * u^2
            v = fmaf(0.8f, v, uu * 0.2f);         // v' (independent chain)
            float vc = v * (0.52f * SQRT_SCALE);  // 8.32 * v'

            float t  = fmaf(K, K, uus);           // 256 * (k^2 + u^2)
            t = fminf(t, TMAX_F);
            float tf = t + MAGIC;                 // round-to-nearest index
            unsigned idx = __float_as_uint(tf) & 0x3FFFu;
            float fi = tf - MAGIC;
            float frac = t - fi;                  // in [-0.5, 0.5]
            float2 pr = s_tbl[idx];
            float g  = fmaf(frac, pr.y, pr.x);
            float a  = fmaf(0.28f, g, 0.8f);
            float cc = g * vc;
            K = fmaf(K, a, cc);                   // K' = 16*k'
            srow[j] = K * 0.13125f;               // z = 2.1*k' = K * (2.1/16)
        }
        __syncwarp();
        // coalesced flush: each warp writes its 32 rows, 32 timesteps
        int t0 = c * 32;
        #pragma unroll 4
        for (int jr = 0; jr < 32; ++jr) {
            int lr = wbase + jr;
            int grow = blockIdx.x * 128 + lr;
            out[(size_t)grow * (T_DIM + 1) + 1 + t0 + lane] = s_out[lr * 33 + lane];
        }
        __syncwarp();
    };

    loadch(ua, 0);
    #pragma unroll 1
    for (int c = 0; c < T_DIM / 32; c += 2) {
        loadch(ub, c + 1);
        compute(ua, c);
        if (c + 2 < T_DIM / 32) loadch(ua, c + 2);
        compute(ub, c + 1);
    }
}

// ---------------------------------------------------------------------------
extern "C" void kernel_launch(void* const* d_in, const int* in_sizes, int n_in,
                              void* d_out, int out_size) {
    const float* u = (const float*)d_in[0];
    float* out = (float*)d_out;

    static const int smem_bytes = 2 * TBL_N * (int)sizeof(float) + 128 * 33 * (int)sizeof(float);
    cudaFuncSetAttribute(scan_kernel, cudaFuncAttributeMaxDynamicSharedMemorySize, smem_bytes);

    gl_nodes_kernel<<<1, 64>>>();
    table_val_kernel<<<TBL_N / 256, 256>>>();
    table_slope_kernel<<<TBL_N / 256, 256>>>();
    scan_kernel<<<B_DIM / 128, 128, smem_bytes>>>(u, out);
}

// round 2
// speedup vs baseline: 1.3733x; 1.3733x over previous
#include <cuda_runtime.h>
#include <math.h>

// ---------------------------------------------------------------------------
// OneDimEquivalent scan:
//   s = k^2 + u^2 ; g(s) = (1/sqrt(2pi)) \int_{-5}^{5} sech^2(sqrt(s) z) e^{-z^2/2} dz
//   v' = 0.8 v + 0.2 u ; k' = 0.8 k + g*(0.28 k + 0.52 v') ; z = 2.1 k'
// g is a smooth univariate function of s -> shared-memory LUT (value+slope),
// built on-device with trapezoid quadrature (spectrally accurate for this
// integrand; no Gauss node solve needed).
// Critical chain per step (state pre-scaled K = 16 k so index = fma(K,K,uusM)):
//   FMA(idx) -> IMAD(addr, magic-bits trick) -> LDS.32 -> FMA(g) -> FMA(K')
// ---------------------------------------------------------------------------

#define B_DIM 4096
#define T_DIM 4096
#define TBL_N 16384
#define SCALE_S 256.0f        // index = SCALE_S * s ; covers s in [0, 64]
#define SQRT_SCALE 16.0f
#define MAGIC 12582912.0f     // 1.5 * 2^23
#define UUS_CAP 15800.0f      // off-chain clamp on 256*u^2 (u <= ~7.85 sigma)
#define INV_SQRT_2PI 0.3989422804014327f

#define NQ 96                 // trapezoid intervals on [0, 5]

__device__ float g_qw[NQ + 1];    // combined weights: 2/sqrt(2pi) * w_j * exp(-z_j^2/2)
__device__ float g_val[TBL_N];
__device__ float g_slp[TBL_N];

// ---------------------------------------------------------------------------
// Kernel 1: quadrature weights (trapezoid nodes z_j = j*h, h = 5/NQ)
// ---------------------------------------------------------------------------
__global__ void qw_kernel() {
    int j = threadIdx.x;
    if (j > NQ) return;
    const float h = 5.0f / (float)NQ;
    float z = h * (float)j;
    float w = (j == 0 || j == NQ) ? 0.5f * h : h;
    g_qw[j] = 2.0f * INV_SQRT_2PI * w * __expf(-0.5f * z * z);
}

// ---------------------------------------------------------------------------
// Kernel 2: table values  g(s_i),  s_i = i / 256
// sech^2(x) = 4 e^{-2x} / (1 + e^{-2x})^2   (x >= 0; underflow-safe)
// ---------------------------------------------------------------------------
__global__ void table_val_kernel() {
    int i = blockIdx.x * blockDim.x + threadIdx.x;
    if (i >= TBL_N) return;
    float s = (float)i * (1.0f / SCALE_S);
    float d = sqrtf(s);
    const float h = 5.0f / (float)NQ;
    float dz = d * h;
    float x = 0.0f;
    float acc = 0.0f;
    #pragma unroll 4
    for (int j = 0; j <= NQ; ++j) {
        float e = __expf(-2.0f * x);
        float t = 1.0f + e;
        float inv = __fdividef(1.0f, t);
        float sech2 = 4.0f * e * inv * inv;
        acc = fmaf(g_qw[j], sech2, acc);
        x += dz;
    }
    g_val[i] = acc;
}

// ---------------------------------------------------------------------------
// Kernel 3: slopes (centered difference per index step)
// ---------------------------------------------------------------------------
__global__ void table_slope_kernel() {
    int i = blockIdx.x * blockDim.x + threadIdx.x;
    if (i >= TBL_N) return;
    float sl;
    if (i == 0)              sl = g_val[1] - g_val[0];
    else if (i == TBL_N - 1) sl = g_val[TBL_N - 1] - g_val[TBL_N - 2];
    else                     sl = 0.5f * (g_val[i + 1] - g_val[i - 1]);
    g_slp[i] = sl;
}

// ---------------------------------------------------------------------------
// Main scan kernel. 32 blocks x 128 threads = 4096 rows (1 thread / row).
// Shared: value table (64KB) + slope table (64KB) + staging (stride 33).
// ---------------------------------------------------------------------------
__global__ __launch_bounds__(128, 1)
void scan_kernel(const float* __restrict__ u, float* __restrict__ out) {
    extern __shared__ float smem[];
    float* s_val = smem;
    float* s_slp = smem + TBL_N;
    float* s_out = smem + 2 * TBL_N;   // 128 * 33 floats

    // cooperative table load (float4)
    {
        const float4* gv = (const float4*)g_val;
        const float4* gs = (const float4*)g_slp;
        float4* sv = (float4*)s_val;
        float4* ss = (float4*)s_slp;
        #pragma unroll 4
        for (int i = threadIdx.x; i < TBL_N / 4; i += 128) {
            sv[i] = gv[i];
            ss[i] = gs[i];
        }
    }
    __syncthreads();

    const int tid   = threadIdx.x;
    const int lane  = tid & 31;
    const int wbase = tid & ~31;
    const int row   = blockIdx.x * 128 + tid;

    // Magic addressing bases: tf_bits = 0x4B400000 | idx ; tf_bits*4 mod 2^32
    // = 0x2D000000 + 4*idx, so addr = tf_bits*4 + (smem_addr - 0x2D000000).
    const unsigned vbase = (unsigned)__cvta_generic_to_shared(s_val) - 0x2D000000u;
    const unsigned sbase = (unsigned)__cvta_generic_to_shared(s_slp) - 0x2D000000u;

    const float* urow = u + (size_t)row * T_DIM;
    out[(size_t)row * (T_DIM + 1)] = 0.0f;

    float* srow = s_out + tid * 33;

    float K = 0.0f, v = 0.0f;     // K = 16*k
    float ua[32], ub[32];

    auto loadch = [&](float (&b)[32], int c) {
        const float4* p = (const float4*)(urow + c * 32);
        #pragma unroll
        for (int q = 0; q < 8; ++q) {
            float4 t = p[q];
            b[4*q+0] = t.x; b[4*q+1] = t.y; b[4*q+2] = t.z; b[4*q+3] = t.w;
        }
    };

    auto compute = [&](const float (&b)[32], int c) {
        #pragma unroll
        for (int j = 0; j < 32; ++j) {
            float uu   = b[j];
            float us   = uu * SQRT_SCALE;
            float uus  = fminf(us * us, UUS_CAP);   // off-chain
            float uusM = uus + MAGIC;               // off-chain
            v = fmaf(0.8f, v, uu * 0.2f);           // v' (own 4-cyc chain)
            float vc  = v * (0.52f * SQRT_SCALE);   // 8.32 * v'
            float w   = fmaf(0.28f, K, vc);         // parallel with index chain
            float K08 = 0.8f * K;                   // parallel

            float tf = fmaf(K, K, uusM);            // rounded index + MAGIC
            unsigned tb = __float_as_uint(tf);
            float fi   = tf - MAGIC;                // off-chain vs LDS
            float frac = fmaf(K, K, uus) - fi;      // exact-ish residual

            float val, slp;
            unsigned av = tb * 4u + vbase;
            unsigned as_ = tb * 4u + sbase;
            asm volatile("ld.shared.f32 %0, [%1];" : "=f"(val) : "r"(av));
            asm volatile("ld.shared.f32 %0, [%1];" : "=f"(slp) : "r"(as_));

            float g = fmaf(frac, slp, val);
            K = fmaf(g, w, K08);                    // K' = 16*k'
            srow[j] = K * 0.13125f;                 // z = 2.1*k' = K*(2.1/16)
        }
        __syncwarp();
        int t0 = c * 32;
        #pragma unroll 4
        for (int jr = 0; jr < 32; ++jr) {
            int lr = wbase + jr;
            int grow = blockIdx.x * 128 + lr;
            out[(size_t)grow * (T_DIM + 1) + 1 + t0 + lane] = s_out[lr * 33 + lane];
        }
        __syncwarp();
    };

    loadch(ua, 0);
    #pragma unroll 1
    for (int c = 0; c < T_DIM / 32; c += 2) {
        loadch(ub, c + 1);
        compute(ua, c);
        if (c + 2 < T_DIM / 32) loadch(ua, c + 2);
        compute(ub, c + 1);
    }
}

// ---------------------------------------------------------------------------
extern "C" void kernel_launch(void* const* d_in, const int* in_sizes, int n_in,
                              void* d_out, int out_size) {
    const float* u = (const float*)d_in[0];
    float* out = (float*)d_out;

    static const int smem_bytes =
        2 * TBL_N * (int)sizeof(float) + 128 * 33 * (int)sizeof(float);
    cudaFuncSetAttribute(scan_kernel, cudaFuncAttributeMaxDynamicSharedMemorySize, smem_bytes);

    qw_kernel<<<1, 128>>>();
    table_val_kernel<<<TBL_N / 256, 256>>>();
    table_slope_kernel<<<TBL_N / 256, 256>>>();
    scan_kernel<<<B_DIM / 128, 128, smem_bytes>>>(u, out);
}

// round 3
// speedup vs baseline: 3.3256x; 2.4215x over previous
#include <cuda_runtime.h>
#include <math.h>

// ---------------------------------------------------------------------------
// OneDimEquivalent scan, time-chunked.
//   s = k^2 + u^2 ; g(s) = (1/sqrt(2pi)) \int sech^2(sqrt(s) z) e^{-z^2/2} dz
//   v' = 0.8 v + 0.2 u ; k' = 0.8 k + g*(0.28 k + 0.52 v') ; z = 2.1 k'
// Dynamics are contracting (0.8 v-decay; k Jacobian 0.8+0.28g<~1), so the
// time axis is split into C=8 chunks of 512 steps; each chunk c>0 starts from
// (0,0) at t=512c-512 and burns 512 warm-up steps (truncation ~rho^512).
// Serial length 4096 -> 1024; 256 blocks, 2 per SM.
// g LUT: 8192 cells of line coeffs (a,b); g = fma(t, a, b), t = 128*s.
// Chain: FMA(idx) -> IMAD(magic addr) -> LDS.64 -> FMA(g) -> FMA(K').
// ---------------------------------------------------------------------------

#define B_DIM 4096
#define T_DIM 4096
#define CHUNKS 8
#define LCH 512               // steps written per chunk
#define WARM 512              // warm-up steps for chunks c>0
#define TBL_N 8192
#define SCALE_S 128.0f        // index t = 128*s ; covers s in [0, 64]
#define SQRT_SCALE 11.313708498984761f   // sqrt(128)
#define VC_CONST 5.8831284194720758f     // 0.52*sqrt(128)
#define ZC_CONST 0.18561553006114707f    // 2.1/sqrt(128)
#define MAGIC 12582912.0f     // 1.5 * 2^23
#define UUS_CAP 7900.0f       // off-chain clamp on 128*u^2
#define INV_SQRT_2PI 0.3989422804014327f
#define NQ 96                 // trapezoid intervals on [0, 5]

__device__ float  g_qw[NQ + 1];
__device__ float  g_val[TBL_N];
__device__ float2 g_tab[TBL_N];   // (a, b): g ~= a*t + b on cell

// ---------------------------------------------------------------------------
__global__ void qw_kernel() {
    int j = threadIdx.x;
    if (j > NQ) return;
    const float h = 5.0f / (float)NQ;
    float z = h * (float)j;
    float w = (j == 0 || j == NQ) ? 0.5f * h : h;
    g_qw[j] = 2.0f * INV_SQRT_2PI * w * __expf(-0.5f * z * z);
}

// table values g(s_i), s_i = i/128 ; sech^2(x) = 4 e^{-2x}/(1+e^{-2x})^2
__global__ void table_val_kernel() {
    int i = blockIdx.x * blockDim.x + threadIdx.x;
    if (i >= TBL_N) return;
    float s = (float)i * (1.0f / SCALE_S);
    float d = sqrtf(s);
    const float h = 5.0f / (float)NQ;
    float dz = d * h;
    float x = 0.0f;
    float acc = 0.0f;
    #pragma unroll 4
    for (int j = 0; j <= NQ; ++j) {
        float e = __expf(-2.0f * x);
        float inv = __fdividef(1.0f, 1.0f + e);
        acc = fmaf(g_qw[j], 4.0f * e * inv * inv, acc);
        x += dz;
    }
    g_val[i] = acc;
}

// line coefficients: a = centered slope per index, b = val - a*i
__global__ void table_coef_kernel() {
    int i = blockIdx.x * blockDim.x + threadIdx.x;
    if (i >= TBL_N) return;
    float a;
    if (i == 0)              a = g_val[1] - g_val[0];
    else if (i == TBL_N - 1) a = g_val[TBL_N - 1] - g_val[TBL_N - 2];
    else                     a = 0.5f * (g_val[i + 1] - g_val[i - 1]);
    g_tab[i].x = a;
    g_tab[i].y = g_val[i] - a * (float)i;
}

// ---------------------------------------------------------------------------
// Scan: grid (32 rowblocks, 8 chunks) x 128 threads. 2 blocks/SM.
// Shared: coeff table (64KB) + per-warp staging (stride 33).
// State pre-scaled K = sqrt(128)*k so index t = fma(K,K,uus).
// ---------------------------------------------------------------------------
__global__ __launch_bounds__(128, 2)
void scan_kernel(const float* __restrict__ u, float* __restrict__ out) {
    extern __shared__ float smem[];
    float2* s_tab = (float2*)smem;             // 8192 float2
    float*  s_out = smem + 2 * TBL_N;          // 128 * 33 floats

    {   // cooperative table load
        const float4* gt = (const float4*)g_tab;
        float4* st = (float4*)s_tab;
        #pragma unroll 4
        for (int i = threadIdx.x; i < TBL_N / 2; i += 128) st[i] = gt[i];
    }
    __syncthreads();

    const int tid   = threadIdx.x;
    const int lane  = tid & 31;
    const int wbase = tid & ~31;
    const int rowblk = blockIdx.x;
    const int c      = blockIdx.y;
    const int row    = rowblk * 128 + tid;

    // magic addressing: bits(t+MAGIC)*8 mod 2^32 = 0x5A000000 + 8*idx
    const unsigned tbase = (unsigned)__cvta_generic_to_shared(s_tab) - 0x5A000000u;

    const int t0 = c * LCH - (c ? WARM : 0);   // first simulated step
    const float* urow = u + (size_t)row * T_DIM + t0;
    if (c == 0) out[(size_t)row * (T_DIM + 1)] = 0.0f;

    float* srow = s_out + tid * 33;

    float K = 0.0f, v = 0.0f;
    float ua[32], ub[32];

    auto loadch = [&](float (&b)[32], int grp) {
        const float4* p = (const float4*)(urow + grp * 32);
        #pragma unroll
        for (int q = 0; q < 8; ++q) {
            float4 t = p[q];
            b[4*q+0] = t.x; b[4*q+1] = t.y; b[4*q+2] = t.z; b[4*q+3] = t.w;
        }
    };

    // one recurrence step; returns nothing, updates K, v
    auto step = [&](float uu) {
        float us   = uu * SQRT_SCALE;
        float uus  = fminf(us * us, UUS_CAP);   // off-chain
        float uusM = uus + MAGIC;               // off-chain
        v = fmaf(0.8f, v, 0.2f * uu);           // independent 4-cyc chain
        float vc  = v * VC_CONST;               // 0.52*sqrt(128)*v'
        float w   = fmaf(0.28f, K, vc);         // parallel with index chain
        float K08 = 0.8f * K;                   // parallel
        float tf  = fmaf(K, K, uusM);           // round-to-int index + MAGIC
        float t   = fmaf(K, K, uus);            // unrounded index (parallel)
        unsigned addr = __float_as_uint(tf) * 8u + tbase;
        float a, b2;
        asm volatile("ld.shared.v2.f32 {%0,%1}, [%2];"
                     : "=f"(a), "=f"(b2) : "r"(addr));
        float g = fmaf(t, a, b2);
        K = fmaf(g, w, K08);                    // K' = sqrt(128)*k'
    };

    auto computeN = [&](const float (&b)[32]) {   // warm-up: no writes
        #pragma unroll
        for (int j = 0; j < 32; ++j) step(b[j]);
    };

    auto computeW = [&](const float (&b)[32], int grp) {  // write phase
        #pragma unroll
        for (int j = 0; j < 32; ++j) {
            step(b[j]);
            srow[j] = K * ZC_CONST;             // z = 2.1*k'
        }
        __syncwarp();
        int tg = t0 + grp * 32;                 // global start time of group
        #pragma unroll 4
        for (int jr = 0; jr < 32; ++jr) {
            int lr = wbase + jr;
            int grow = rowblk * 128 + lr;
            out[(size_t)grow * (T_DIM + 1) + 1 + tg + lane] = s_out[lr * 33 + lane];
        }
        __syncwarp();
    };

    const int nwarm_g = c ? (WARM / 32) : 0;    // 16 or 0
    const int nend_g  = nwarm_g + LCH / 32;     // +16

    loadch(ua, 0);
    int grp = 0;
    #pragma unroll 1
    for (; grp < nwarm_g; grp += 2) {           // warm-up (even count)
        loadch(ub, grp + 1);
        computeN(ua);
        loadch(ua, grp + 2);                    // preloads first write group
        computeN(ub);
    }
    #pragma unroll 1
    for (; grp < nend_g; grp += 2) {            // write phase
        loadch(ub, grp + 1);
        computeW(ua, grp);
        if (grp + 2 < nend_g) loadch(ua, grp + 2);
        computeW(ub, grp + 1);
    }
}

// ---------------------------------------------------------------------------
extern "C" void kernel_launch(void* const* d_in, const int* in_sizes, int n_in,
                              void* d_out, int out_size) {
    const float* u = (const float*)d_in[0];
    float* out = (float*)d_out;

    static const int smem_bytes =
        2 * TBL_N * (int)sizeof(float) + 128 * 33 * (int)sizeof(float);
    cudaFuncSetAttribute(scan_kernel, cudaFuncAttributeMaxDynamicSharedMemorySize, smem_bytes);

    qw_kernel<<<1, 128>>>();
    table_val_kernel<<<TBL_N / 256, 256>>>();
    table_coef_kernel<<<TBL_N / 256, 256>>>();
    scan_kernel<<<dim3(B_DIM / 128, CHUNKS), 128, smem_bytes>>>(u, out);
}